// round 12
// baseline (speedup 1.0000x reference)
#include <cuda_runtime.h>
#include <cuda_bf16.h>
#include <cstdint>
#include <math.h>

#define S      512
#define BATCH  64
#define TLEN   1024
#define OBS_N  32000
#define NTHREADS 256
#define JH     256              // j-columns per CTA (cluster of 2)
#define LOG2E 1.4426950408889634f
#define LN2   0.6931471805599453f
#define L2Q   15.988706f        // log2(255*255)

// ---------------- device scratch ---------------------------------------------
__device__ float g_lseRow[S];
__device__ float g_mT[S];
__device__ float g_lseObs[S];
__device__ float g_Cfold[S];                 // mT - lseObs
__device__ float g_initAdd[S];               // log_softmax(prior) - lseObs
// quantized expT, per-rank copy with CTA-local i-chunk order:
// addr = rank*131072 + c*4096 + j_local*16 + b
//   c<16 : global i = rank*256   + 16*c      + b   (own half)
//   c>=16: global i = (1-rank)*256 + 16*(c-16) + b (peer half)
__device__ unsigned char g_expTq[2 * 32 * 4096];

// ---------------- helpers -----------------------------------------------------
__device__ __forceinline__ float ex2_fast(float x) {   // MUFU.EX2
    float r;
    asm("ex2.approx.ftz.f32 %0, %1;" : "=f"(r) : "f"(x));
    return r;
}
__device__ __forceinline__ uint32_t smem_u32(const void* p) {
    uint32_t a;
    asm("{ .reg .u64 t; cvta.to.shared.u64 t, %1; cvt.u32.u64 %0, t; }"
        : "=r"(a) : "l"(p));
    return a;
}
__device__ __forceinline__ uint32_t mapa_u32(uint32_t a, uint32_t rank) {
    uint32_t d;
    asm("mapa.shared::cluster.u32 %0, %1, %2;" : "=r"(d) : "r"(a), "r"(rank));
    return d;
}
__device__ __forceinline__ void st_cluster_f32(uint32_t a, float v) {
    asm volatile("st.shared::cluster.f32 [%0], %1;" :: "r"(a), "f"(v) : "memory");
}
__device__ __forceinline__ void mbar_init(uint32_t a, unsigned cnt) {
    asm volatile("mbarrier.init.shared.b64 [%0], %1;" :: "r"(a), "r"(cnt) : "memory");
}
__device__ __forceinline__ void mbar_arrive_cluster(uint32_t a) {
    asm volatile("mbarrier.arrive.release.cluster.shared::cluster.b64 _, [%0];"
                 :: "r"(a) : "memory");
}
__device__ __forceinline__ void mbar_wait_cluster(uint32_t a, unsigned parity) {
    unsigned done;
    asm volatile(
        "{\n\t.reg .pred p;\n\t"
        "mbarrier.try_wait.parity.acquire.cluster.shared::cta.b64 p, [%1], %2;\n\t"
        "selp.b32 %0, 1, 0, p;\n\t}"
        : "=r"(done) : "r"(a), "r"(parity) : "memory");
    if (!done) {
        asm volatile(
            "{\n\t.reg .pred P1;\n\t"
            "WAIT_LOOP_%=:\n\t"
            "mbarrier.try_wait.parity.acquire.cluster.shared::cta.b64 P1, [%0], %1, 0x989680;\n\t"
            "@P1 bra.uni WAIT_DONE_%=;\n\t"
            "bra.uni WAIT_LOOP_%=;\n\t"
            "WAIT_DONE_%=:\n\t}"
            :: "r"(a), "r"(parity) : "memory");
    }
}
#define CLUSTER_SYNC() do { \
    asm volatile("barrier.cluster.arrive.aligned;" ::: "memory"); \
    asm volatile("barrier.cluster.wait.aligned;"   ::: "memory"); \
} while (0)

template <int NW>
__device__ __forceinline__ float blkMax(float v, float* red) {
    #pragma unroll
    for (int o = 16; o > 0; o >>= 1) v = fmaxf(v, __shfl_xor_sync(0xffffffffu, v, o));
    int w = threadIdx.x >> 5;
    if ((threadIdx.x & 31) == 0) red[w] = v;
    __syncthreads();
    float m = red[0];
    #pragma unroll
    for (int k = 1; k < NW; ++k) m = fmaxf(m, red[k]);
    __syncthreads();
    return m;
}
template <int NW>
__device__ __forceinline__ float blkSum(float v, float* red) {
    #pragma unroll
    for (int o = 16; o > 0; o >>= 1) v += __shfl_xor_sync(0xffffffffu, v, o);
    int w = threadIdx.x >> 5;
    if ((threadIdx.x & 31) == 0) red[w] = v;
    __syncthreads();
    float m = 0.f;
    #pragma unroll
    for (int k = 0; k < NW; ++k) m += red[k];
    __syncthreads();
    return m;
}

// ---------------- precompute kernels ------------------------------------------
__global__ void k_rowlse(const float* __restrict__ ST) {
    __shared__ float red[8];
    int i = blockIdx.x, t = threadIdx.x;
    float x0 = ST[i * S + t], x1 = ST[i * S + t + 256];
    float M = blkMax<8>(fmaxf(x0, x1), red);
    float Ssum = blkSum<8>(expf(x0 - M) + expf(x1 - M), red);
    if (t == 0) g_lseRow[i] = M + logf(Ssum);
}
__global__ void k_colmax(const float* __restrict__ ST) {
    int j = blockIdx.x * blockDim.x + threadIdx.x;
    float m = -1e30f;
    for (int i = 0; i < S; ++i) m = fmaxf(m, ST[i * S + j] - g_lseRow[i]);
    g_mT[j] = m;
}
// quantize expT into the per-rank chunked layout
__global__ void k_expTq(const float* __restrict__ ST) {
    int i = blockIdx.x;                      // global i
    float l = g_lseRow[i];
    for (int j = threadIdx.x; j < S; j += 256) {
        float e = expf(ST[i * S + j] - l - g_mT[j]);
        unsigned q = __float2uint_rn(fminf(e, 1.f) * 255.f);
        int r = j >> 8, jl = j & 255;
        int ihalf = i >> 8, il = i & 255;
        int c = ((ihalf == r) ? 0 : 16) + (il >> 4);
        int b = il & 15;
        g_expTq[r * 131072 + c * 4096 + jl * 16 + b] = (unsigned char)q;
    }
}
__global__ void k_obslse(const float* __restrict__ OT) {
    __shared__ float red[8];
    int s = blockIdx.x, t = threadIdx.x;
    const float* row = OT + (size_t)s * OBS_N;
    float m = -1e30f;
    for (int k = t; k < OBS_N; k += 256) m = fmaxf(m, row[k]);
    float M = blkMax<8>(m, red);
    float acc = 0.f;
    for (int k = t; k < OBS_N; k += 256) acc += expf(row[k] - M);
    float Ssum = blkSum<8>(acc, red);
    if (t == 0) {
        float lse = M + logf(Ssum);
        g_lseObs[s] = lse;
        g_Cfold[s]  = g_mT[s] - lse;
    }
}
__global__ void k_prior(const float* __restrict__ prior) {
    __shared__ float red[16];
    int t = threadIdx.x;
    float p = prior[t];
    float M = blkMax<16>(p, red);
    float Ssum = blkSum<16>(expf(p - M), red);
    float lse = M + logf(Ssum);
    g_initAdd[t] = (p - lse) - g_lseObs[t];
}

// ---------------- forward kernel ------------------------------------------------
// 256 threads, cluster of 2 (j-split), int8/dp4a matvec, thread t <-> j_local t.
// Per step: B(wait exch k-1; m2 -> quantize alpha to u8) | sync | matvec (32
// chunks dp4a, full 512 i, no cross-warp reduction) | E(raw, ship, arrive) | sync.
//
// SMEM (bytes):
//  [0,131072)        sTq   u8 [32 c][256 j][16 b]
//  [131072,131584)   sAq   u8 [512] (chunk order: own 0..255, peer 256..511)
//  [131584,133760)   sRecv f32 [2][272] ([0..255]=raw, [256..263]=warp maxes)
//  [133760,137856)   sOb   int [1024]
//  [137856,137888)   sRed  f32 [8]
//  [137888,137904)   mbar  2 x u64
#define OFF_AQ   131072
#define OFF_RECV 131584
#define OFF_OB   133760
#define OFF_RED  137856
#define OFF_MB   137888
#define SMEM_TOTAL 137920
#define RSTRIDE 272

__global__ void __launch_bounds__(NTHREADS, 1) __cluster_dims__(2, 1, 1)
k_forward(const int* __restrict__ obs, const float* __restrict__ OT,
          float* __restrict__ out) {
    extern __shared__ char smem[];
    unsigned char* sTq   = reinterpret_cast<unsigned char*>(smem);
    unsigned char* sAq   = reinterpret_cast<unsigned char*>(smem + OFF_AQ);
    float*         sRecv = reinterpret_cast<float*>(smem + OFF_RECV);
    int*           sOb   = reinterpret_cast<int*>(smem + OFF_OB);
    float*         sRed  = reinterpret_cast<float*>(smem + OFF_RED);

    const int t    = threadIdx.x;
    const int rank = blockIdx.x & 1;
    const int b    = blockIdx.x >> 1;
    const int wid  = t >> 5, oct = t & 31;

    const uint32_t mbLoc    = smem_u32(smem + OFF_MB);
    const uint32_t mbPeer   = mapa_u32(mbLoc, (uint32_t)(rank ^ 1));
    const uint32_t recvPeer = mapa_u32(smem_u32(sRecv), (uint32_t)(rank ^ 1));

    if (t == 0) { mbar_init(mbLoc, NTHREADS); mbar_init(mbLoc + 8, NTHREADS); }

    const int ownBase  = rank * JH;
    const int peerBase = (rank ^ 1) * JH;

    // one-time SMEM fill: sTq (already in final layout in gmem)
    {
        const uint4* src = reinterpret_cast<const uint4*>(g_expTq + rank * 131072);
        uint4* dst = reinterpret_cast<uint4*>(sTq);
        for (int k = t; k < 131072 / 16; k += NTHREADS) dst[k] = src[k];
    }
    for (int k = t; k < TLEN; k += NTHREADS) sOb[k] = obs[b * TLEN + k];
    __syncthreads();

    // ---- init: alpha0 raw (log2-offset), ship exchange 0 ----
    float E2;
    float rawOwn;
    const float cf = g_Cfold[ownBase + t];
    {
        int o0 = sOb[0];
        float aO = __ldg(OT + (size_t)(ownBase + t) * OBS_N + o0) + g_initAdd[ownBase + t];
        float aP = __ldg(OT + (size_t)(peerBase + t) * OBS_N + o0) + g_initAdd[peerBase + t];
        float M = blkMax<8>(fmaxf(aO, aP), sRed);
        E2 = M * LOG2E;
        rawOwn = ex2_fast((aO - M) * LOG2E);
        st_cluster_f32(recvPeer + (unsigned)t * 4u, rawOwn);
        float m = rawOwn;
        #pragma unroll
        for (int o = 16; o > 0; o >>= 1)
            m = fmaxf(m, __shfl_xor_sync(0xffffffffu, m, o));
        if (oct == 0) {
            st_cluster_f32(recvPeer + (unsigned)(256 + wid) * 4u, m);
            sRed[wid] = m;
        }
    }
    CLUSTER_SYNC();                      // peer mbar inits + init stores visible
    mbar_arrive_cluster(mbPeer);         // exchange 0 on slot 0
    __syncthreads();

    const float* wPtr = OT + (size_t)(ownBase + t) * OBS_N;
    int slot = 0;
    int ph0 = 0, ph1 = 0;

    #pragma unroll 1
    for (int step = 1; step <= TLEN; ++step) {
        const int ot = (step < TLEN) ? sOb[step] : 0;
        const float w = __ldg(wPtr + ot);        // prefetch: overlaps the wait

        // ---- B: consume exchange(step-1), quantize alpha ----
        mbar_wait_cluster(mbLoc + slot * 8, (unsigned)(slot ? ph1 : ph0));
        if (slot) ph1 ^= 1; else ph0 ^= 1;
        const unsigned rbase = (unsigned)(slot * RSTRIDE);
        float M2 = 1e-30f;
        #pragma unroll
        for (int k = 0; k < 8; ++k) M2 = fmaxf(M2, sRed[k]);
        #pragma unroll
        for (int k = 0; k < 8; ++k) M2 = fmaxf(M2, sRecv[rbase + 256 + k]);
        int m2 = (__float_as_int(M2) >> 23) - 127;
        // qs = 255 * 2^-(m2+1); max quantized value in [128,255)
        float qs = __int_as_float((126 - m2) << 23) * 255.f;
        E2 += (float)(m2 + 1);
        sAq[t]       = (unsigned char)__float2uint_rn(rawOwn * qs);
        sAq[256 + t] = (unsigned char)__float2uint_rn(sRecv[rbase + t] * qs);
        __syncthreads();

        // ---- matvec: full 512 i via 32 dp4a chunks ----
        unsigned acc0 = 0, acc1 = 0, acc2 = 0, acc3 = 0;
        {
            const uint4* aPtr = reinterpret_cast<const uint4*>(sAq);
            const uint4* ePtr = reinterpret_cast<const uint4*>(sTq + t * 16);
            #pragma unroll
            for (int c = 0; c < 32; ++c) {
                uint4 av = aPtr[c];                 // broadcast (16 a-bytes)
                uint4 ev = ePtr[c * 256];           // c*4096 bytes
                acc0 = __dp4a(av.x, ev.x, acc0);
                acc1 = __dp4a(av.y, ev.y, acc1);
                acc2 = __dp4a(av.z, ev.z, acc2);
                acc3 = __dp4a(av.w, ev.w, acc3);
            }
        }
        float P = (float)((acc0 + acc1) + (acc2 + acc3));

        // ---- E: raw alpha(step), ship exchange(step) ----
        float raw = P * ex2_fast(fmaf(w + cf, LOG2E, -L2Q));
        const int sendSlot = slot ^ 1;
        const unsigned sbase = (unsigned)(sendSlot * RSTRIDE);
        st_cluster_f32(recvPeer + (sbase + t) * 4u, raw);
        float m = raw;
        #pragma unroll
        for (int o = 16; o > 0; o >>= 1)
            m = fmaxf(m, __shfl_xor_sync(0xffffffffu, m, o));
        if (oct == 0) {
            st_cluster_f32(recvPeer + (sbase + 256 + wid) * 4u, m);
            sRed[wid] = m;
        }
        mbar_arrive_cluster(mbPeer + sendSlot * 8);
        rawOwn = raw;
        __syncthreads();   // orders sAq reads (matvec) before next B's writes; sRed
        slot = sendSlot;
    }

    // ---- final: own + peer raw (exchange TLEN pending) ----
    mbar_wait_cluster(mbLoc + slot * 8, (unsigned)(slot ? ph1 : ph0));
    float total = blkSum<8>(rawOwn + sRecv[slot * RSTRIDE + t], sRed);
    if (rank == 0 && t == 0) out[b] = logf(total) + E2 * LN2;
    CLUSTER_SYNC();
}

// ---------------- launch -------------------------------------------------------
extern "C" void kernel_launch(void* const* d_in, const int* in_sizes, int n_in,
                              void* d_out, int out_size) {
    const int*   obs   = (const int*)d_in[0];
    const float* ST    = (const float*)d_in[1];
    const float* OT    = (const float*)d_in[2];
    const float* prior = (const float*)d_in[3];
    float* out = (float*)d_out;

    cudaFuncSetAttribute(k_forward, cudaFuncAttributeMaxDynamicSharedMemorySize,
                         SMEM_TOTAL);

    k_rowlse<<<S, 256>>>(ST);
    k_colmax<<<4, 128>>>(ST);
    k_expTq<<<S, 256>>>(ST);
    k_obslse<<<S, 256>>>(OT);
    k_prior<<<1, S>>>(prior);
    k_forward<<<BATCH * 2, NTHREADS, SMEM_TOTAL>>>(obs, OT, out);
}

// round 13
// speedup vs baseline: 1.1287x; 1.1287x over previous
#include <cuda_runtime.h>
#include <cuda_bf16.h>
#include <cstdint>
#include <math.h>

#define S      512
#define BATCH  64
#define TLEN   1024
#define OBS_N  32000
#define NTHREADS 256
#define JH     256              // j-columns per CTA (cluster of 2)
#define LOG2E 1.4426950408889634f
#define LN2   0.6931471805599453f
#define L2Q   15.988707f        // log2(255*255)

// ---------------- device scratch ---------------------------------------------
__device__ float g_lseRow[S];
__device__ float g_mT[S];
__device__ float g_lseObs[S];
// quantized expT, per-rank copy with CTA-local i-chunk order:
// addr = rank*131072 + c*4096 + j_local*16 + b
//   c<16 : global i = rank*256     + 16*c      + b   (own half)
//   c>=16: global i = (1-rank)*256 + 16*(c-16) + b   (peer half)
__device__ unsigned char g_expTq[2 * 32 * 4096];

// ---------------- helpers -----------------------------------------------------
__device__ __forceinline__ float ex2_fast(float x) {   // MUFU.EX2
    float r;
    asm("ex2.approx.ftz.f32 %0, %1;" : "=f"(r) : "f"(x));
    return r;
}
__device__ __forceinline__ unsigned redux_max_u32(unsigned v) {
    unsigned r;
    asm("redux.sync.max.u32 %0, %1, 0xffffffff;" : "=r"(r) : "r"(v));
    return r;
}
__device__ __forceinline__ uint32_t smem_u32(const void* p) {
    uint32_t a;
    asm("{ .reg .u64 t; cvta.to.shared.u64 t, %1; cvt.u32.u64 %0, t; }"
        : "=r"(a) : "l"(p));
    return a;
}
__device__ __forceinline__ uint32_t mapa_u32(uint32_t a, uint32_t rank) {
    uint32_t d;
    asm("mapa.shared::cluster.u32 %0, %1, %2;" : "=r"(d) : "r"(a), "r"(rank));
    return d;
}
__device__ __forceinline__ void st_cluster_u8(uint32_t a, unsigned v) {
    asm volatile("st.shared::cluster.u8 [%0], %1;" :: "r"(a), "r"(v) : "memory");
}
__device__ __forceinline__ void st_cluster_u32(uint32_t a, unsigned v) {
    asm volatile("st.shared::cluster.u32 [%0], %1;" :: "r"(a), "r"(v) : "memory");
}
__device__ __forceinline__ void mbar_init(uint32_t a, unsigned cnt) {
    asm volatile("mbarrier.init.shared.b64 [%0], %1;" :: "r"(a), "r"(cnt) : "memory");
}
__device__ __forceinline__ void mbar_arrive_cluster(uint32_t a) {
    asm volatile("mbarrier.arrive.release.cluster.shared::cluster.b64 _, [%0];"
                 :: "r"(a) : "memory");
}
__device__ __forceinline__ void mbar_wait_cluster(uint32_t a, unsigned parity) {
    unsigned done;
    asm volatile(
        "{\n\t.reg .pred p;\n\t"
        "mbarrier.try_wait.parity.acquire.cluster.shared::cta.b64 p, [%1], %2;\n\t"
        "selp.b32 %0, 1, 0, p;\n\t}"
        : "=r"(done) : "r"(a), "r"(parity) : "memory");
    if (!done) {
        asm volatile(
            "{\n\t.reg .pred P1;\n\t"
            "WAIT_LOOP_%=:\n\t"
            "mbarrier.try_wait.parity.acquire.cluster.shared::cta.b64 P1, [%0], %1, 0x989680;\n\t"
            "@P1 bra.uni WAIT_DONE_%=;\n\t"
            "bra.uni WAIT_LOOP_%=;\n\t"
            "WAIT_DONE_%=:\n\t}"
            :: "r"(a), "r"(parity) : "memory");
    }
}
#define CLUSTER_SYNC() do { \
    asm volatile("barrier.cluster.arrive.aligned;" ::: "memory"); \
    asm volatile("barrier.cluster.wait.aligned;"   ::: "memory"); \
} while (0)

template <int NW>
__device__ __forceinline__ float blkMax(float v, float* red) {
    #pragma unroll
    for (int o = 16; o > 0; o >>= 1) v = fmaxf(v, __shfl_xor_sync(0xffffffffu, v, o));
    int w = threadIdx.x >> 5;
    if ((threadIdx.x & 31) == 0) red[w] = v;
    __syncthreads();
    float m = red[0];
    #pragma unroll
    for (int k = 1; k < NW; ++k) m = fmaxf(m, red[k]);
    __syncthreads();
    return m;
}
template <int NW>
__device__ __forceinline__ float blkSum(float v, float* red) {
    #pragma unroll
    for (int o = 16; o > 0; o >>= 1) v += __shfl_xor_sync(0xffffffffu, v, o);
    int w = threadIdx.x >> 5;
    if ((threadIdx.x & 31) == 0) red[w] = v;
    __syncthreads();
    float m = 0.f;
    #pragma unroll
    for (int k = 0; k < NW; ++k) m += red[k];
    __syncthreads();
    return m;
}

// ---------------- precompute (3 launches so k_forward = my launch #4) ----------
__global__ void k_rowlse(const float* __restrict__ ST) {
    __shared__ float red[8];
    int i = blockIdx.x, t = threadIdx.x;
    float x0 = ST[i * S + t], x1 = ST[i * S + t + 256];
    float M = blkMax<8>(fmaxf(x0, x1), red);
    float Ssum = blkSum<8>(expf(x0 - M) + expf(x1 - M), red);
    if (t == 0) g_lseRow[i] = M + logf(Ssum);
}
__global__ void k_colmax(const float* __restrict__ ST) {
    int j = blockIdx.x * blockDim.x + threadIdx.x;
    float m = -1e30f;
    for (int i = 0; i < S; ++i) m = fmaxf(m, ST[i * S + j] - g_lseRow[i]);
    g_mT[j] = m;
}
// expT quantize (row i=bid) + obs row logsumexp (row s=bid), fused
__global__ void k_pre3(const float* __restrict__ ST, const float* __restrict__ OT) {
    __shared__ float red[8];
    int i = blockIdx.x, t = threadIdx.x;
    // --- expTq ---
    float l = g_lseRow[i];
    for (int j = t; j < S; j += 256) {
        float e = expf(ST[i * S + j] - l - g_mT[j]);
        unsigned q = __float2uint_rn(fminf(e, 1.f) * 255.f);
        int r = j >> 8, jl = j & 255;
        int ihalf = i >> 8, il = i & 255;
        int c = ((ihalf == r) ? 0 : 16) + (il >> 4);
        int b = il & 15;
        g_expTq[r * 131072 + c * 4096 + jl * 16 + b] = (unsigned char)q;
    }
    // --- obs logsumexp (s = i) ---
    const float* row = OT + (size_t)i * OBS_N;
    float m = -1e30f;
    for (int k = t; k < OBS_N; k += 256) m = fmaxf(m, row[k]);
    float M = blkMax<8>(m, red);
    float acc = 0.f;
    for (int k = t; k < OBS_N; k += 256) acc += expf(row[k] - M);
    float Ssum = blkSum<8>(acc, red);
    if (t == 0) g_lseObs[i] = M + logf(Ssum);
}

// ---------------- forward kernel ------------------------------------------------
// 256 threads, cluster of 2 (j-split), int8/dp4a, QUANTIZED exchange.
// Per step: wait(exch k-1) -> matvec (own bytes from sAqD double buffer, peer
// bytes directly from recv slot) -> combine via 16 per-warp exponents -> raw ->
// redux-max exponent -> quantize -> ship u8 + exps -> arrive -> one syncthreads.
//
// SMEM (bytes):
//  [0,131072)        sTq    u8 [32 c][256 j][16 b]
//  [131072,131584)   sAqD   u8 [2][256]   (own quantized alpha, dbl buf)
//  [131584,131648)   sEoD   u32 [2][8]    (own warp exponents, dbl buf)
//  [131648,132224)   sRecvQ [2][288]: u8 q[256] + u32 exps[8]
//  [132224,136320)   sOb    int [1024]
//  [136320,136352)   sRed   f32 [8]
//  [136352,136368)   mbar   2 x u64
#define OFF_AQ   131072
#define OFF_EO   131584
#define OFF_RQ   131648
#define OFF_OB   132224
#define OFF_RED  136320
#define OFF_MB   136352
#define SMEM_TOTAL 136448
#define RQ_STRIDE 288

__global__ void __launch_bounds__(NTHREADS, 1) __cluster_dims__(2, 1, 1)
k_forward(const int* __restrict__ obs, const float* __restrict__ OT,
          const float* __restrict__ prior, float* __restrict__ out) {
    extern __shared__ char smem[];
    unsigned char* sTq   = reinterpret_cast<unsigned char*>(smem);
    unsigned char* sAqD  = reinterpret_cast<unsigned char*>(smem + OFF_AQ);
    unsigned*      sEoD  = reinterpret_cast<unsigned*>(smem + OFF_EO);
    unsigned char* sRecvQ= reinterpret_cast<unsigned char*>(smem + OFF_RQ);
    int*           sOb   = reinterpret_cast<int*>(smem + OFF_OB);
    float*         sRed  = reinterpret_cast<float*>(smem + OFF_RED);

    const int t    = threadIdx.x;
    const int rank = blockIdx.x & 1;
    const int b    = blockIdx.x >> 1;
    const int wid  = t >> 5;

    const uint32_t mbLoc   = smem_u32(smem + OFF_MB);
    const uint32_t mbPeer  = mapa_u32(mbLoc, (uint32_t)(rank ^ 1));
    const uint32_t rqPeer  = mapa_u32(smem_u32(sRecvQ), (uint32_t)(rank ^ 1));

    if (t == 0) { mbar_init(mbLoc, NTHREADS); mbar_init(mbLoc + 8, NTHREADS); }

    const int ownBase  = rank * JH;
    const int peerBase = (rank ^ 1) * JH;

    // one-time SMEM fill (layout already final in gmem)
    {
        const uint4* src = reinterpret_cast<const uint4*>(g_expTq + rank * 131072);
        uint4* dst = reinterpret_cast<uint4*>(sTq);
        for (int k = t; k < 131072 / 16; k += NTHREADS) dst[k] = src[k];
    }
    for (int k = t; k < TLEN; k += NTHREADS) sOb[k] = obs[b * TLEN + k];
    __syncthreads();

    // ---- init: prior log-softmax (block-wide over 512), alpha0 own half ----
    float E2;
    float rawOwn;
    float cf;
    {
        float p0 = prior[ownBase + t], p1 = prior[peerBase + t];
        float Mp = blkMax<8>(fmaxf(p0, p1), sRed);
        float Sp = blkSum<8>(expf(p0 - Mp) + expf(p1 - Mp), sRed);
        float lseP = Mp + logf(Sp);
        float lo0 = g_lseObs[ownBase + t];
        cf = g_mT[ownBase + t] - lo0;

        int o0 = sOb[0];
        float aO = __ldg(OT + (size_t)(ownBase + t) * OBS_N + o0)
                   + (p0 - lseP) - lo0;
        float aP = __ldg(OT + (size_t)(peerBase + t) * OBS_N + o0)
                   + (p1 - lseP) - g_lseObs[peerBase + t];
        float M = blkMax<8>(fmaxf(aO, aP), sRed);   // cluster-consistent ref
        E2 = M * LOG2E;
        rawOwn = fmaxf(ex2_fast((aO - M) * LOG2E), 1e-35f);

        // quantize own half per warp; write buf 0; ship slot 0
        unsigned bexp = __float_as_uint(rawOwn) >> 23;
        unsigned bw = redux_max_u32(bexp);
        float qsf = __uint_as_float((253u - bw) << 23) * 255.f;
        unsigned q = __float2uint_rn(rawOwn * qsf);
        sAqD[t] = (unsigned char)q;
        st_cluster_u8(rqPeer + (unsigned)t, q);
        if ((t & 31) == 0) {
            sEoD[wid] = bw;
            st_cluster_u32(rqPeer + 256u + (unsigned)wid * 4u, bw);
        }
    }
    CLUSTER_SYNC();                      // peer mbar inits + init stores visible
    mbar_arrive_cluster(mbPeer);         // exchange 0 on slot 0
    __syncthreads();

    const float* wPtr = OT + (size_t)(ownBase + t) * OBS_N;
    int slot = 0;                        // recv slot for step k = (k-1)&1
    int ph0 = 0, ph1 = 0;

    #pragma unroll 1
    for (int step = 1; step <= TLEN; ++step) {
        const int ot = (step < TLEN) ? sOb[step] : 0;
        const float w = __ldg(wPtr + ot);      // hidden under wait+matvec

        // ---- wait exchange(step-1) (per-thread; acquire covers sRecvQ) ----
        mbar_wait_cluster(mbLoc + slot * 8, (unsigned)(slot ? ph1 : ph0));
        if (slot) ph1 ^= 1; else ph0 ^= 1;

        const int rbuf = (step - 1) & 1;

        // ---- matvec: 32 dp4a chunks into 16 per-warp-group accumulators ----
        unsigned acc[16];
        #pragma unroll
        for (int g = 0; g < 16; ++g) acc[g] = 0u;
        {
            const uint4* aOwn = reinterpret_cast<const uint4*>(sAqD + rbuf * 256);
            const uint4* aPr  = reinterpret_cast<const uint4*>(sRecvQ + slot * RQ_STRIDE);
            const uint4* ePtr = reinterpret_cast<const uint4*>(sTq + t * 16);
            #pragma unroll
            for (int c = 0; c < 16; ++c) {
                uint4 av = aOwn[c];
                uint4 ev = ePtr[c * 256];
                unsigned a = acc[c >> 1];
                a = __dp4a(av.x, ev.x, a);
                a = __dp4a(av.y, ev.y, a);
                a = __dp4a(av.z, ev.z, a);
                a = __dp4a(av.w, ev.w, a);
                acc[c >> 1] = a;
            }
            #pragma unroll
            for (int c = 0; c < 16; ++c) {
                uint4 av = aPr[c];
                uint4 ev = ePtr[(16 + c) * 256];
                unsigned a = acc[8 + (c >> 1)];
                a = __dp4a(av.x, ev.x, a);
                a = __dp4a(av.y, ev.y, a);
                a = __dp4a(av.z, ev.z, a);
                a = __dp4a(av.w, ev.w, a);
                acc[8 + (c >> 1)] = a;
            }
        }

        // ---- combine with 16 per-warp exponents ----
        unsigned be[16];
        {
            const unsigned* eo = sEoD + rbuf * 8;
            const unsigned* ep = reinterpret_cast<const unsigned*>(
                sRecvQ + slot * RQ_STRIDE + 256);
            #pragma unroll
            for (int g = 0; g < 8; ++g) { be[g] = eo[g]; be[8 + g] = ep[g]; }
        }
        unsigned bref = be[0];
        #pragma unroll
        for (int g = 1; g < 16; ++g) bref = max(bref, be[g]);
        float P = 0.f;
        #pragma unroll
        for (int g = 0; g < 16; ++g) {
            int d = (int)be[g] - (int)bref;
            d = (d < -126) ? -126 : d;
            P += (float)acc[g] * __uint_as_float((unsigned)(d + 127) << 23);
        }
        E2 += (float)((int)bref - 126);

        // ---- raw alpha(step), quantize, ship exchange(step) ----
        float raw = fmaxf(P * ex2_fast(fmaf(w + cf, LOG2E, -L2Q)), 1e-35f);
        unsigned bexp = __float_as_uint(raw) >> 23;
        unsigned bw = redux_max_u32(bexp);
        float qsf = __uint_as_float((253u - bw) << 23) * 255.f;
        unsigned q = __float2uint_rn(raw * qsf);

        const int sendSlot = slot ^ 1;    // = step&1
        const int wbuf = step & 1;
        sAqD[wbuf * 256 + t] = (unsigned char)q;
        st_cluster_u8(rqPeer + (unsigned)(sendSlot * RQ_STRIDE + t), q);
        if ((t & 31) == 0) {
            sEoD[wbuf * 8 + wid] = bw;
            st_cluster_u32(rqPeer + (unsigned)(sendSlot * RQ_STRIDE + 256 + wid * 4), bw);
        }
        mbar_arrive_cluster(mbPeer + sendSlot * 8);
        rawOwn = raw;
        __syncthreads();                  // bounds skew for sAqD/sEoD reuse
        slot = sendSlot;
    }

    // ---- final: own raw + dequantized peer raw (exchange TLEN pending) ----
    mbar_wait_cluster(mbLoc + slot * 8, (unsigned)(slot ? ph1 : ph0));
    float peerVal;
    {
        unsigned qp = (unsigned)sRecvQ[slot * RQ_STRIDE + t];
        unsigned beg = reinterpret_cast<const unsigned*>(
            sRecvQ + slot * RQ_STRIDE + 256)[wid];
        peerVal = (float)qp * __uint_as_float((beg + 1u) << 23) * (1.f / 255.f);
    }
    float total = blkSum<8>(rawOwn + peerVal, sRed);
    if (rank == 0 && t == 0) out[b] = logf(total) + E2 * LN2;
    CLUSTER_SYNC();
}

// ---------------- launch -------------------------------------------------------
extern "C" void kernel_launch(void* const* d_in, const int* in_sizes, int n_in,
                              void* d_out, int out_size) {
    const int*   obs   = (const int*)d_in[0];
    const float* ST    = (const float*)d_in[1];
    const float* OT    = (const float*)d_in[2];
    const float* prior = (const float*)d_in[3];
    float* out = (float*)d_out;

    cudaFuncSetAttribute(k_forward, cudaFuncAttributeMaxDynamicSharedMemorySize,
                         SMEM_TOTAL);

    k_rowlse<<<S, 256>>>(ST);
    k_colmax<<<4, 128>>>(ST);
    k_pre3<<<S, 256>>>(ST, OT);
    k_forward<<<BATCH * 2, NTHREADS, SMEM_TOTAL>>>(obs, OT, prior, out);
}